// round 3
// baseline (speedup 1.0000x reference)
#include <cuda_runtime.h>
#include <math.h>

#define NMAX   32768
#define KNN    12
#define WID    192
#define CONDD  64
#define IN0    115      // 51 PE + 64 cond
#define MIXD   390      // 192 + 192 + 6
#define NL     4
#define BRP    16       // rows per block, prep
#define BRL    24       // rows per block, layer
#define KTILE  1024
#define NSTRIPE 4
#define NCAND  (NSTRIPE * KNN)   // 48

// ---------------- scratch (device globals; no allocations allowed) ----------
__device__ int   g_knn[NMAX * KNN];
__device__ float g_rel[NMAX * 6];
__device__ float g_h[2][NMAX * WID];
__device__ float g_gamma[NL * WID];
__device__ float g_beta[NL * WID];
__device__ float g_cand_d[NMAX * NCAND];
__device__ int   g_cand_i[NMAX * NCAND];

// ------- kNN stripe pass: per-stripe top-12, batched-8 compare --------------
__global__ void __launch_bounds__(128) knn_stripe_kernel(const float* __restrict__ x,
                                                         int n, int stripe_len) {
    __shared__ float4 tile[KTILE];
    const int row = blockIdx.x * 128 + threadIdx.x;
    const int stripe = blockIdx.y;
    const int col0 = stripe * stripe_len;
    const int col1 = min(col0 + stripe_len, n);

    float xi = 0.f, yi = 0.f, zi = 0.f;
    if (row < n) { xi = x[row * 3 + 0]; yi = x[row * 3 + 1]; zi = x[row * 3 + 2]; }

    float bd[KNN];
    int   bi[KNN];
#pragma unroll
    for (int s = 0; s < KNN; s++) { bd[s] = 1e30f; bi[s] = 0; }
    float worst = 1e30f;
    int   wslot = 0;

    for (int base = col0; base < col1; base += KTILE) {
        __syncthreads();
        for (int u = threadIdx.x; u < KTILE; u += 128) {
            int col = base + u;
            float a = 0.f, b = 0.f, c = 0.f, w = 3e30f;
            if (col < col1) {
                a = x[col * 3 + 0]; b = x[col * 3 + 1]; c = x[col * 3 + 2];
                w = fmaf(a, a, fmaf(b, b, c * c));
            }
            tile[u] = make_float4(a, b, c, w);
        }
        __syncthreads();

        for (int j = 0; j < KTILE; j += 8) {
            float d[8];
#pragma unroll
            for (int u = 0; u < 8; u++) {
                float4 p = tile[j + u];
                // shifted squared distance: |xj|^2 - 2 xi.xj (ordering == true dist)
                d[u] = fmaf(-2.f, fmaf(xi, p.x, fmaf(yi, p.y, zi * p.z)), p.w);
            }
            float m = fminf(fminf(fminf(d[0], d[1]), fminf(d[2], d[3])),
                            fminf(fminf(d[4], d[5]), fminf(d[6], d[7])));
            if (m < worst) {  // rare slow path
#pragma unroll
                for (int u = 0; u < 8; u++) {
                    int col = base + j + u;
                    if (d[u] < worst && col != row) {
#pragma unroll
                        for (int s = 0; s < KNN; s++)
                            if (s == wslot) { bd[s] = d[u]; bi[s] = col; }
                        worst = bd[0]; wslot = 0;
#pragma unroll
                        for (int s = 1; s < KNN; s++)
                            if (bd[s] > worst) { worst = bd[s]; wslot = s; }
                    }
                }
            }
        }
    }
    if (row >= n) return;
#pragma unroll
    for (int s = 0; s < KNN; s++) {
        g_cand_d[row * NCAND + stripe * KNN + s] = bd[s];
        g_cand_i[row * NCAND + stripe * KNN + s] = bi[s];
    }
}

// ------- kNN merge: select global top-12 from 48 candidates + rel stats -----
__global__ void knn_merge_kernel(const float* __restrict__ x, int n) {
    const int row = blockIdx.x * blockDim.x + threadIdx.x;
    if (row >= n) return;

    float bd[KNN];
    int   bi[KNN];
#pragma unroll
    for (int s = 0; s < KNN; s++) { bd[s] = 1e30f; bi[s] = 0; }
    float worst = 1e30f;
    int   wslot = 0;

    for (int q = 0; q < NCAND; q++) {
        float d = g_cand_d[row * NCAND + q];
        if (d < worst) {
            int c = g_cand_i[row * NCAND + q];
#pragma unroll
            for (int s = 0; s < KNN; s++)
                if (s == wslot) { bd[s] = d; bi[s] = c; }
            worst = bd[0]; wslot = 0;
#pragma unroll
            for (int s = 1; s < KNN; s++)
                if (bd[s] > worst) { worst = bd[s]; wslot = s; }
        }
    }

    float xi = x[row * 3 + 0], yi = x[row * 3 + 1], zi = x[row * 3 + 2];
    float sx = 0.f, sy = 0.f, sz = 0.f, qx = 0.f, qy = 0.f, qz = 0.f;
#pragma unroll
    for (int s = 0; s < KNN; s++) {
        int c = bi[s];
        g_knn[row * KNN + s] = c;
        float rx = x[c * 3 + 0] - xi;
        float ry = x[c * 3 + 1] - yi;
        float rz = x[c * 3 + 2] - zi;
        sx += rx; sy += ry; sz += rz;
        qx = fmaf(rx, rx, qx); qy = fmaf(ry, ry, qy); qz = fmaf(rz, rz, qz);
    }
    const float inv = 1.f / (float)KNN;
    float mx = sx * inv, my = sy * inv, mz = sz * inv;
    g_rel[row * 6 + 0] = mx;
    g_rel[row * 6 + 1] = my;
    g_rel[row * 6 + 2] = mz;
    g_rel[row * 6 + 3] = sqrtf(fmaxf(qx * inv - mx * mx, 0.f));
    g_rel[row * 6 + 4] = sqrtf(fmaxf(qy * inv - my * my, 0.f));
    g_rel[row * 6 + 5] = sqrtf(fmaxf(qz * inv - mz * mz, 0.f));
}

// ---------------- FiLM gamma/beta (depends only on z); one block per layer --
__global__ void film_kernel(const float* __restrict__ z,
                            const float* __restrict__ Wg, const float* __restrict__ bg,
                            const float* __restrict__ Wb, const float* __restrict__ bb) {
    int c = threadIdx.x;  // 192
    int li = blockIdx.x;  // 4
    float ga = bg[li * WID + c];
    float be = bb[li * WID + c];
    for (int k = 0; k < CONDD; k++) {
        float zk = z[k];
        ga = fmaf(zk, Wg[(li * CONDD + k) * WID + c], ga);
        be = fmaf(zk, Wb[(li * CONDD + k) * WID + c], be);
    }
    g_gamma[li * WID + c] = ga;
    g_beta[li * WID + c]  = be;
}

__device__ __forceinline__ float silu(float a) {
    return a / (1.f + expf(-a));
}

// ---------------- prep: fourier PE + concat z + first dense + silu ----------
__global__ void prep_kernel(const float* __restrict__ x, const float* __restrict__ z,
                            const float* __restrict__ B0, const float* __restrict__ B1,
                            const float* __restrict__ B2,
                            const float* __restrict__ Wp, const float* __restrict__ bp,
                            int n) {
    __shared__ float fs[BRP * 120];  // stride 120 (16B-aligned float4 rows)
    const int row0 = blockIdx.x * BRP;
    const int tid = threadIdx.x;  // 192

    for (int e = tid; e < BRP * IN0; e += 192) {
        int r = e / IN0, i = e % IN0;
        int row = row0 + r;
        float v = 0.f;
        if (row < n) {
            if (i < 48) {
                int g = i >> 4, w = i & 15, col = w & 7;
                const float* B = (g == 0) ? B0 : ((g == 1) ? B1 : B2);
                float x0 = x[row * 3 + 0], x1 = x[row * 3 + 1], x2 = x[row * 3 + 2];
                float dot = fmaf(x0, B[col], fmaf(x1, B[8 + col], x2 * B[16 + col]));
                v = (w < 8) ? sinf(dot) : cosf(dot);
            } else if (i < 51) {
                v = x[row * 3 + (i - 48)];
            } else {
                v = z[i - 51];
            }
        }
        fs[r * 120 + i] = v;
    }
    for (int e = tid; e < BRP * 5; e += 192) {
        int r = e / 5, i = 115 + e % 5;
        fs[r * 120 + i] = 0.f;
    }
    __syncthreads();

    const int c = tid;
    float acc[BRP];
    float b = bp[c];
#pragma unroll
    for (int r = 0; r < BRP; r++) acc[r] = b;

    for (int ic = 0; ic < 28; ic++) {  // 112 of 115
        int i = ic * 4;
        float w0 = Wp[(i + 0) * WID + c];
        float w1 = Wp[(i + 1) * WID + c];
        float w2 = Wp[(i + 2) * WID + c];
        float w3 = Wp[(i + 3) * WID + c];
#pragma unroll
        for (int r = 0; r < BRP; r++) {
            float4 m = *(const float4*)&fs[r * 120 + i];
            acc[r] = fmaf(m.x, w0, acc[r]);
            acc[r] = fmaf(m.y, w1, acc[r]);
            acc[r] = fmaf(m.z, w2, acc[r]);
            acc[r] = fmaf(m.w, w3, acc[r]);
        }
    }
    for (int i = 112; i < 115; i++) {
        float w0 = Wp[i * WID + c];
#pragma unroll
        for (int r = 0; r < BRP; r++) acc[r] = fmaf(fs[r * 120 + i], w0, acc[r]);
    }

#pragma unroll
    for (int r = 0; r < BRP; r++) {
        int row = row0 + r;
        if (row < n) g_h[0][row * WID + c] = silu(acc[r]);
    }
}

// ---------------- one graph layer: gather+mean, mix GEMM, silu, FiLM --------
__global__ void __launch_bounds__(192) layer_kernel(int src, int li,
                             const float* __restrict__ Wl_all,
                             const float* __restrict__ bl_all,
                             int n) {
    __shared__ float ms[BRL * 392];  // [h(192) | agg(192) | rel(6) | pad(2)]
    const float* __restrict__ hin = g_h[src];
    float* __restrict__ hout = g_h[1 - src];
    const float* __restrict__ Wl = Wl_all + (size_t)li * MIXD * WID;

    const int row0 = blockIdx.x * BRL;
    const int c = threadIdx.x;  // 192
    const float inv = 1.f / (float)KNN;

    for (int r = 0; r < BRL; r++) {
        int row = row0 + r;
        float hv = 0.f, s = 0.f;
        if (row < n) {
            hv = hin[row * WID + c];
#pragma unroll
            for (int j = 0; j < KNN; j++) {
                int nb = g_knn[row * KNN + j];
                s += hin[nb * WID + c];
            }
        }
        ms[r * 392 + c]       = hv;
        ms[r * 392 + 192 + c] = s * inv;
    }
    for (int e = c; e < BRL * 8; e += 192) {
        int r = e / 8, i = e % 8;
        int row = row0 + r;
        ms[r * 392 + 384 + i] = (i < 6 && row < n) ? g_rel[row * 6 + i] : 0.f;
    }
    __syncthreads();

    float acc[BRL];
    float b = bl_all[li * WID + c];
#pragma unroll
    for (int r = 0; r < BRL; r++) acc[r] = b;

    // double-buffered weight registers to cover LDG latency
    float w0 = Wl[0 * WID + c];
    float w1 = Wl[1 * WID + c];
    float w2 = Wl[2 * WID + c];
    float w3 = Wl[3 * WID + c];
    for (int ic = 0; ic < 97; ic++) {  // 388 of 390
        int i = ic * 4;
        float n0 = 0.f, n1 = 0.f, n2 = 0.f, n3 = 0.f;
        if (ic < 96) {
            n0 = Wl[(i + 4) * WID + c];
            n1 = Wl[(i + 5) * WID + c];
            n2 = Wl[(i + 6) * WID + c];
            n3 = Wl[(i + 7) * WID + c];
        }
#pragma unroll
        for (int r = 0; r < BRL; r++) {
            float4 m = *(const float4*)&ms[r * 392 + i];
            acc[r] = fmaf(m.x, w0, acc[r]);
            acc[r] = fmaf(m.y, w1, acc[r]);
            acc[r] = fmaf(m.z, w2, acc[r]);
            acc[r] = fmaf(m.w, w3, acc[r]);
        }
        w0 = n0; w1 = n1; w2 = n2; w3 = n3;
    }
    for (int i = 388; i < 390; i++) {
        float wv = Wl[i * WID + c];
#pragma unroll
        for (int r = 0; r < BRL; r++) acc[r] = fmaf(ms[r * 392 + i], wv, acc[r]);
    }

    const float ga = g_gamma[li * WID + c];
    const float be = g_beta[li * WID + c];
#pragma unroll
    for (int r = 0; r < BRL; r++) {
        int row = row0 + r;
        if (row < n) hout[row * WID + c] = fmaf(silu(acc[r]), ga, be);
    }
}

// ---------------- output head: (h @ Wout + bout) * 0.01 ---------------------
__global__ void out_kernel(const float* __restrict__ Wout,
                           const float* __restrict__ bout,
                           float* __restrict__ out, int n) {
    const float* __restrict__ hin = g_h[0];  // after 4 layers: 0->1->0->1->0
    int gtid = blockIdx.x * blockDim.x + threadIdx.x;
    int warp = gtid >> 5;
    int lane = threadIdx.x & 31;
    if (warp >= n) return;
    float a0 = 0.f, a1 = 0.f, a2 = 0.f;
    for (int i = lane; i < WID; i += 32) {
        float h = hin[warp * WID + i];
        a0 = fmaf(h, Wout[i * 3 + 0], a0);
        a1 = fmaf(h, Wout[i * 3 + 1], a1);
        a2 = fmaf(h, Wout[i * 3 + 2], a2);
    }
#pragma unroll
    for (int o = 16; o; o >>= 1) {
        a0 += __shfl_down_sync(0xffffffffu, a0, o);
        a1 += __shfl_down_sync(0xffffffffu, a1, o);
        a2 += __shfl_down_sync(0xffffffffu, a2, o);
    }
    if (lane == 0) {
        out[warp * 3 + 0] = (a0 + bout[0]) * 0.01f;
        out[warp * 3 + 1] = (a1 + bout[1]) * 0.01f;
        out[warp * 3 + 2] = (a2 + bout[2]) * 0.01f;
    }
}

// ---------------- launch -----------------------------------------------------
extern "C" void kernel_launch(void* const* d_in, const int* in_sizes, int n_in,
                              void* d_out, int out_size) {
    const float* x    = (const float*)d_in[0];
    const float* z    = (const float*)d_in[1];
    const float* B0   = (const float*)d_in[2];
    const float* B1   = (const float*)d_in[3];
    const float* B2   = (const float*)d_in[4];
    const float* Wp   = (const float*)d_in[5];
    const float* bp   = (const float*)d_in[6];
    const float* Wl   = (const float*)d_in[7];
    const float* bl   = (const float*)d_in[8];
    const float* Wg   = (const float*)d_in[9];
    const float* bg   = (const float*)d_in[10];
    const float* Wb   = (const float*)d_in[11];
    const float* bb   = (const float*)d_in[12];
    const float* Wout = (const float*)d_in[13];
    const float* bout = (const float*)d_in[14];
    float* out = (float*)d_out;

    const int n = in_sizes[0] / 3;

    // stripe length: ceil(n/NSTRIPE) rounded up to a KTILE multiple
    int stripe_len = (n + NSTRIPE - 1) / NSTRIPE;
    stripe_len = (stripe_len + KTILE - 1) / KTILE * KTILE;

    dim3 kgrid((n + 127) / 128, NSTRIPE);
    knn_stripe_kernel<<<kgrid, 128>>>(x, n, stripe_len);
    knn_merge_kernel<<<(n + 127) / 128, 128>>>(x, n);

    film_kernel<<<NL, WID>>>(z, Wg, bg, Wb, bb);
    prep_kernel<<<(n + BRP - 1) / BRP, WID>>>(x, z, B0, B1, B2, Wp, bp, n);

    int src = 0;
    for (int li = 0; li < NL; li++) {
        layer_kernel<<<(n + BRL - 1) / BRL, WID>>>(src, li, Wl, bl, n);
        src = 1 - src;
    }

    out_kernel<<<(n * 32 + 255) / 256, 256>>>(Wout, bout, out, n);
}

// round 4
// speedup vs baseline: 2.0968x; 2.0968x over previous
#include <cuda_runtime.h>
#include <math.h>
#include <float.h>

#define NMAX   32768
#define KNN    12
#define WID    192
#define CONDD  64
#define IN0    115      // 51 PE + 64 cond
#define MIXD   390      // 192 + 192 + 6
#define NL     4
#define BRP    16       // rows per block, prep
#define BRL    24       // rows per block, layer

#define GRID   32
#define CELLS  (GRID * GRID * GRID)
#define GMINF  (-4.0f)
#define GH     0.25f
#define GINVH  4.0f

// ---------------- scratch (device globals; no allocations allowed) ----------
__device__ int    g_knn[NMAX * KNN];
__device__ float  g_rel[NMAX * 6];
__device__ float  g_h[2][NMAX * WID];
__device__ float  g_gamma[NL * WID];
__device__ float  g_beta[NL * WID];

__device__ int    g_cnt[CELLS];
__device__ int    g_start[CELLS + 1];
__device__ int    g_cell[NMAX];
__device__ int    g_rank[NMAX];
__device__ float4 g_pts4[NMAX];       // sorted coords + |p|^2
__device__ int    g_sorted_orig[NMAX];

// ---------------- grid build -------------------------------------------------
__device__ __forceinline__ int cell_coord(float v) {
    int c = (int)floorf((v - GMINF) * GINVH);
    return min(GRID - 1, max(0, c));
}

__global__ void grid_zero_kernel() {
    int i = blockIdx.x * blockDim.x + threadIdx.x;
    if (i < CELLS) g_cnt[i] = 0;
}

__global__ void grid_hist_kernel(const float* __restrict__ x, int n) {
    int i = blockIdx.x * blockDim.x + threadIdx.x;
    if (i >= n) return;
    int cx = cell_coord(x[i * 3 + 0]);
    int cy = cell_coord(x[i * 3 + 1]);
    int cz = cell_coord(x[i * 3 + 2]);
    int c = (cz * GRID + cy) * GRID + cx;
    g_cell[i] = c;
    g_rank[i] = atomicAdd(&g_cnt[c], 1);
}

__global__ void grid_scan_kernel() {  // single block, 1024 threads, 32 cells each
    __shared__ int sh[1024];
    int tid = threadIdx.x;
    int base = tid * 32;
    int s = 0;
    for (int k = 0; k < 32; k++) s += g_cnt[base + k];
    sh[tid] = s;
    __syncthreads();
    for (int off = 1; off < 1024; off <<= 1) {
        int v = (tid >= off) ? sh[tid - off] : 0;
        __syncthreads();
        sh[tid] += v;
        __syncthreads();
    }
    int run = sh[tid] - s;  // exclusive base
    for (int k = 0; k < 32; k++) {
        g_start[base + k] = run;
        run += g_cnt[base + k];
    }
    if (tid == 1023) g_start[CELLS] = sh[1023];
}

__global__ void grid_scatter_kernel(const float* __restrict__ x, int n) {
    int i = blockIdx.x * blockDim.x + threadIdx.x;
    if (i >= n) return;
    float px = x[i * 3 + 0], py = x[i * 3 + 1], pz = x[i * 3 + 2];
    int pos = g_start[g_cell[i]] + g_rank[i];
    g_pts4[pos] = make_float4(px, py, pz, fmaf(px, px, fmaf(py, py, pz * pz)));
    g_sorted_orig[pos] = i;
}

// ---------------- kNN search: expanding shells with exact stop bound --------
__global__ void knn_search_kernel(int n) {
    const int t = blockIdx.x * blockDim.x + threadIdx.x;
    if (t >= n) return;
    const float4 q = g_pts4[t];
    const float qsq = q.w;
    const int cx = cell_coord(q.x);
    const int cy = cell_coord(q.y);
    const int cz = cell_coord(q.z);

    float bd[KNN];
    int   bi[KNN];
#pragma unroll
    for (int s = 0; s < KNN; s++) { bd[s] = 1e30f; bi[s] = 0; }
    float worst = 1e30f;
    int   wslot = 0;

    for (int r = 0; r < GRID; r++) {
        const int zlo = max(cz - r, 0), zhi = min(cz + r, GRID - 1);
        const int ylo = max(cy - r, 0), yhi = min(cy + r, GRID - 1);
        const int xlo = max(cx - r, 0), xhi = min(cx + r, GRID - 1);
        for (int iz = zlo; iz <= zhi; iz++) {
            const bool zedge = (iz == cz - r) || (iz == cz + r);
            for (int iy = ylo; iy <= yhi; iy++) {
                const bool yedge = (iy == cy - r) || (iy == cy + r);
                const int rowc = (iz * GRID + iy) * GRID;
                int j0, j1;
                if (zedge || yedge) {
                    j0 = g_start[rowc + xlo];
                    j1 = g_start[rowc + xhi + 1];
                } else {
                    // interior plane row: only x endpoints are new cells
                    j0 = 0; j1 = 0;
                    if (cx - r >= 0) {
                        int c = rowc + (cx - r);
                        j0 = g_start[c]; j1 = g_start[c + 1];
                    }
                    if (cx + r <= GRID - 1) {
                        int c = rowc + (cx + r);
                        int a0 = g_start[c], a1 = g_start[c + 1];
                        for (int j = a0; j < a1; j++) {
                            float4 p = g_pts4[j];
                            float d = qsq + p.w
                                    - 2.f * fmaf(q.x, p.x, fmaf(q.y, p.y, q.z * p.z));
                            if (d < worst && j != t) {
#pragma unroll
                                for (int s = 0; s < KNN; s++)
                                    if (s == wslot) { bd[s] = d; bi[s] = j; }
                                worst = bd[0]; wslot = 0;
#pragma unroll
                                for (int s = 1; s < KNN; s++)
                                    if (bd[s] > worst) { worst = bd[s]; wslot = s; }
                            }
                        }
                    }
                }
                for (int j = j0; j < j1; j++) {
                    float4 p = g_pts4[j];
                    float d = qsq + p.w
                            - 2.f * fmaf(q.x, p.x, fmaf(q.y, p.y, q.z * p.z));
                    if (d < worst && j != t) {
#pragma unroll
                        for (int s = 0; s < KNN; s++)
                            if (s == wslot) { bd[s] = d; bi[s] = j; }
                        worst = bd[0]; wslot = 0;
#pragma unroll
                        for (int s = 1; s < KNN; s++)
                            if (bd[s] > worst) { worst = bd[s]; wslot = s; }
                    }
                }
            }
        }
        // exact stop bound: min distance from q to unscanned region
        float b = FLT_MAX;
        if (zlo > 0)        b = fminf(b, q.z - (GMINF + zlo * GH));
        if (zhi < GRID - 1) b = fminf(b, (GMINF + (zhi + 1) * GH) - q.z);
        if (ylo > 0)        b = fminf(b, q.y - (GMINF + ylo * GH));
        if (yhi < GRID - 1) b = fminf(b, (GMINF + (yhi + 1) * GH) - q.y);
        if (xlo > 0)        b = fminf(b, q.x - (GMINF + xlo * GH));
        if (xhi < GRID - 1) b = fminf(b, (GMINF + (xhi + 1) * GH) - q.x);
        if (worst <= b * b) break;
    }

    // write indices (original ids) + relative-coordinate stats
    const int orig = g_sorted_orig[t];
    float sx = 0.f, sy = 0.f, sz = 0.f, qx = 0.f, qy = 0.f, qz = 0.f;
#pragma unroll
    for (int s = 0; s < KNN; s++) {
        int pos = bi[s];
        float4 p = g_pts4[pos];
        g_knn[orig * KNN + s] = g_sorted_orig[pos];
        float rx = p.x - q.x;
        float ry = p.y - q.y;
        float rz = p.z - q.z;
        sx += rx; sy += ry; sz += rz;
        qx = fmaf(rx, rx, qx); qy = fmaf(ry, ry, qy); qz = fmaf(rz, rz, qz);
    }
    const float inv = 1.f / (float)KNN;
    float mx = sx * inv, my = sy * inv, mz = sz * inv;
    g_rel[orig * 6 + 0] = mx;
    g_rel[orig * 6 + 1] = my;
    g_rel[orig * 6 + 2] = mz;
    g_rel[orig * 6 + 3] = sqrtf(fmaxf(qx * inv - mx * mx, 0.f));
    g_rel[orig * 6 + 4] = sqrtf(fmaxf(qy * inv - my * my, 0.f));
    g_rel[orig * 6 + 5] = sqrtf(fmaxf(qz * inv - mz * mz, 0.f));
}

// ---------------- FiLM gamma/beta (depends only on z); one block per layer --
__global__ void film_kernel(const float* __restrict__ z,
                            const float* __restrict__ Wg, const float* __restrict__ bg,
                            const float* __restrict__ Wb, const float* __restrict__ bb) {
    int c = threadIdx.x;  // 192
    int li = blockIdx.x;  // 4
    float ga = bg[li * WID + c];
    float be = bb[li * WID + c];
    for (int k = 0; k < CONDD; k++) {
        float zk = z[k];
        ga = fmaf(zk, Wg[(li * CONDD + k) * WID + c], ga);
        be = fmaf(zk, Wb[(li * CONDD + k) * WID + c], be);
    }
    g_gamma[li * WID + c] = ga;
    g_beta[li * WID + c]  = be;
}

__device__ __forceinline__ float silu(float a) {
    return a / (1.f + expf(-a));
}

// ---------------- prep: fourier PE + concat z + first dense + silu ----------
__global__ void prep_kernel(const float* __restrict__ x, const float* __restrict__ z,
                            const float* __restrict__ B0, const float* __restrict__ B1,
                            const float* __restrict__ B2,
                            const float* __restrict__ Wp, const float* __restrict__ bp,
                            int n) {
    __shared__ float fs[BRP * 120];  // stride 120 (16B-aligned float4 rows)
    const int row0 = blockIdx.x * BRP;
    const int tid = threadIdx.x;  // 192

    for (int e = tid; e < BRP * IN0; e += 192) {
        int r = e / IN0, i = e % IN0;
        int row = row0 + r;
        float v = 0.f;
        if (row < n) {
            if (i < 48) {
                int g = i >> 4, w = i & 15, col = w & 7;
                const float* B = (g == 0) ? B0 : ((g == 1) ? B1 : B2);
                float x0 = x[row * 3 + 0], x1 = x[row * 3 + 1], x2 = x[row * 3 + 2];
                float dot = fmaf(x0, B[col], fmaf(x1, B[8 + col], x2 * B[16 + col]));
                v = (w < 8) ? sinf(dot) : cosf(dot);
            } else if (i < 51) {
                v = x[row * 3 + (i - 48)];
            } else {
                v = z[i - 51];
            }
        }
        fs[r * 120 + i] = v;
    }
    for (int e = tid; e < BRP * 5; e += 192) {
        int r = e / 5, i = 115 + e % 5;
        fs[r * 120 + i] = 0.f;
    }
    __syncthreads();

    const int c = tid;
    float acc[BRP];
    float b = bp[c];
#pragma unroll
    for (int r = 0; r < BRP; r++) acc[r] = b;

    for (int ic = 0; ic < 28; ic++) {  // 112 of 115
        int i = ic * 4;
        float w0 = Wp[(i + 0) * WID + c];
        float w1 = Wp[(i + 1) * WID + c];
        float w2 = Wp[(i + 2) * WID + c];
        float w3 = Wp[(i + 3) * WID + c];
#pragma unroll
        for (int r = 0; r < BRP; r++) {
            float4 m = *(const float4*)&fs[r * 120 + i];
            acc[r] = fmaf(m.x, w0, acc[r]);
            acc[r] = fmaf(m.y, w1, acc[r]);
            acc[r] = fmaf(m.z, w2, acc[r]);
            acc[r] = fmaf(m.w, w3, acc[r]);
        }
    }
    for (int i = 112; i < 115; i++) {
        float w0 = Wp[i * WID + c];
#pragma unroll
        for (int r = 0; r < BRP; r++) acc[r] = fmaf(fs[r * 120 + i], w0, acc[r]);
    }

#pragma unroll
    for (int r = 0; r < BRP; r++) {
        int row = row0 + r;
        if (row < n) g_h[0][row * WID + c] = silu(acc[r]);
    }
}

// ---------------- one graph layer: gather+mean, mix GEMM, silu, FiLM --------
__global__ void __launch_bounds__(192) layer_kernel(int src, int li,
                             const float* __restrict__ Wl_all,
                             const float* __restrict__ bl_all,
                             int n) {
    __shared__ float ms[BRL * 392];  // [h(192) | agg(192) | rel(6) | pad(2)]
    const float* __restrict__ hin = g_h[src];
    float* __restrict__ hout = g_h[1 - src];
    const float* __restrict__ Wl = Wl_all + (size_t)li * MIXD * WID;

    const int row0 = blockIdx.x * BRL;
    const int c = threadIdx.x;  // 192
    const float inv = 1.f / (float)KNN;

    for (int r = 0; r < BRL; r++) {
        int row = row0 + r;
        float hv = 0.f, s = 0.f;
        if (row < n) {
            hv = hin[row * WID + c];
#pragma unroll
            for (int j = 0; j < KNN; j++) {
                int nb = g_knn[row * KNN + j];
                s += hin[nb * WID + c];
            }
        }
        ms[r * 392 + c]       = hv;
        ms[r * 392 + 192 + c] = s * inv;
    }
    for (int e = c; e < BRL * 8; e += 192) {
        int r = e / 8, i = e % 8;
        int row = row0 + r;
        ms[r * 392 + 384 + i] = (i < 6 && row < n) ? g_rel[row * 6 + i] : 0.f;
    }
    __syncthreads();

    float acc[BRL];
    float b = bl_all[li * WID + c];
#pragma unroll
    for (int r = 0; r < BRL; r++) acc[r] = b;

    // double-buffered weight registers to cover LDG latency
    float w0 = Wl[0 * WID + c];
    float w1 = Wl[1 * WID + c];
    float w2 = Wl[2 * WID + c];
    float w3 = Wl[3 * WID + c];
    for (int ic = 0; ic < 97; ic++) {  // 388 of 390
        int i = ic * 4;
        float n0 = 0.f, n1 = 0.f, n2 = 0.f, n3 = 0.f;
        if (ic < 96) {
            n0 = Wl[(i + 4) * WID + c];
            n1 = Wl[(i + 5) * WID + c];
            n2 = Wl[(i + 6) * WID + c];
            n3 = Wl[(i + 7) * WID + c];
        }
#pragma unroll
        for (int r = 0; r < BRL; r++) {
            float4 m = *(const float4*)&ms[r * 392 + i];
            acc[r] = fmaf(m.x, w0, acc[r]);
            acc[r] = fmaf(m.y, w1, acc[r]);
            acc[r] = fmaf(m.z, w2, acc[r]);
            acc[r] = fmaf(m.w, w3, acc[r]);
        }
        w0 = n0; w1 = n1; w2 = n2; w3 = n3;
    }
    for (int i = 388; i < 390; i++) {
        float wv = Wl[i * WID + c];
#pragma unroll
        for (int r = 0; r < BRL; r++) acc[r] = fmaf(ms[r * 392 + i], wv, acc[r]);
    }

    const float ga = g_gamma[li * WID + c];
    const float be = g_beta[li * WID + c];
#pragma unroll
    for (int r = 0; r < BRL; r++) {
        int row = row0 + r;
        if (row < n) hout[row * WID + c] = fmaf(silu(acc[r]), ga, be);
    }
}

// ---------------- output head: (h @ Wout + bout) * 0.01 ---------------------
__global__ void out_kernel(const float* __restrict__ Wout,
                           const float* __restrict__ bout,
                           float* __restrict__ out, int n) {
    const float* __restrict__ hin = g_h[0];  // after 4 layers: 0->1->0->1->0
    int gtid = blockIdx.x * blockDim.x + threadIdx.x;
    int warp = gtid >> 5;
    int lane = threadIdx.x & 31;
    if (warp >= n) return;
    float a0 = 0.f, a1 = 0.f, a2 = 0.f;
    for (int i = lane; i < WID; i += 32) {
        float h = hin[warp * WID + i];
        a0 = fmaf(h, Wout[i * 3 + 0], a0);
        a1 = fmaf(h, Wout[i * 3 + 1], a1);
        a2 = fmaf(h, Wout[i * 3 + 2], a2);
    }
#pragma unroll
    for (int o = 16; o; o >>= 1) {
        a0 += __shfl_down_sync(0xffffffffu, a0, o);
        a1 += __shfl_down_sync(0xffffffffu, a1, o);
        a2 += __shfl_down_sync(0xffffffffu, a2, o);
    }
    if (lane == 0) {
        out[warp * 3 + 0] = (a0 + bout[0]) * 0.01f;
        out[warp * 3 + 1] = (a1 + bout[1]) * 0.01f;
        out[warp * 3 + 2] = (a2 + bout[2]) * 0.01f;
    }
}

// ---------------- launch -----------------------------------------------------
extern "C" void kernel_launch(void* const* d_in, const int* in_sizes, int n_in,
                              void* d_out, int out_size) {
    const float* x    = (const float*)d_in[0];
    const float* z    = (const float*)d_in[1];
    const float* B0   = (const float*)d_in[2];
    const float* B1   = (const float*)d_in[3];
    const float* B2   = (const float*)d_in[4];
    const float* Wp   = (const float*)d_in[5];
    const float* bp   = (const float*)d_in[6];
    const float* Wl   = (const float*)d_in[7];
    const float* bl   = (const float*)d_in[8];
    const float* Wg   = (const float*)d_in[9];
    const float* bg   = (const float*)d_in[10];
    const float* Wb   = (const float*)d_in[11];
    const float* bb   = (const float*)d_in[12];
    const float* Wout = (const float*)d_in[13];
    const float* bout = (const float*)d_in[14];
    float* out = (float*)d_out;

    const int n = in_sizes[0] / 3;

    // spatial-grid kNN
    grid_zero_kernel<<<(CELLS + 255) / 256, 256>>>();
    grid_hist_kernel<<<(n + 255) / 256, 256>>>(x, n);
    grid_scan_kernel<<<1, 1024>>>();
    grid_scatter_kernel<<<(n + 255) / 256, 256>>>(x, n);
    knn_search_kernel<<<(n + 127) / 128, 128>>>(n);

    film_kernel<<<NL, WID>>>(z, Wg, bg, Wb, bb);
    prep_kernel<<<(n + BRP - 1) / BRP, WID>>>(x, z, B0, B1, B2, Wp, bp, n);

    int src = 0;
    for (int li = 0; li < NL; li++) {
        layer_kernel<<<(n + BRL - 1) / BRL, WID>>>(src, li, Wl, bl, n);
        src = 1 - src;
    }

    out_kernel<<<(n * 32 + 255) / 256, 256>>>(Wout, bout, out, n);
}